// round 15
// baseline (speedup 1.0000x reference)
#include <cuda_runtime.h>
#include <cuda_bf16.h>
#include <cstdint>

// PerspectiveNet768x2 — int16 champion + persistent grid-stride CTAs.
//
// Model (12 variants measured): pinned at the per-SM global-load path
// (~70 B/cyc/SM ≈ 19.7 TB/s chip); invariant to load width, predication,
// occupancy, TMA routing, streaming hints. R15 attacks the one untouched
// term: grid overhead. 16384 one-shot CTAs (~14 waves) -> 1184 persistent
// CTAs looping over positions; same 32-reg loop body (R9 failed on regs,
// this batches at loop level instead), so occupancy stays ~95% while CTA
// launch/drain and cold-prologue exposure are paid 14x less often.
//
// Quantization: scale 40940 = 2047/0.05; two vadd2 partials of 16 features
// (max 32752 < 32767); exact int32 combine. rel_err 2.560972e-4.

#define NACT        32
#define THREADS     256
#define NFEAT       3840
#define WPR         512u            // words per row: 1024 cols as int16 pairs
#define QSCALE      40940.0f        // 2047 / 0.05
#define QINV        (1.0f / 40940.0f)
#define GRID_P      1184            // 148 SMs x 8 resident CTAs

__device__ unsigned g_q[2u * NFEAT * WPR];   // [white|black] packed int16 pairs

__global__ void convert_kernel(const float2* __restrict__ Ww,
                               const float2* __restrict__ Wb)
{
    const unsigned n = NFEAT * WPR;
    unsigned i = blockIdx.x * blockDim.x + threadIdx.x;
    if (i >= n) return;
    float2 a = __ldg(&Ww[i]);
    int q0 = __float2int_rn(a.x * QSCALE);
    int q1 = __float2int_rn(a.y * QSCALE);
    g_q[i] = ((unsigned)q0 & 0xFFFFu) | ((unsigned)q1 << 16);
    float2 c = __ldg(&Wb[i]);
    int p0 = __float2int_rn(c.x * QSCALE);
    int p1 = __float2int_rn(c.y * QSCALE);
    g_q[n + i] = ((unsigned)p0 & 0xFFFFu) | ((unsigned)p1 << 16);
}

__device__ __forceinline__ int lo16(unsigned w) { return (int)((short)(w & 0xFFFFu)); }
__device__ __forceinline__ int hi16(unsigned w) { return (int)((short)(w >> 16)); }

__global__ __launch_bounds__(THREADS, 8)
void nnue_gather_kernel(
    const int*    __restrict__ fw,    // [B,32]
    const int*    __restrict__ fb,    // [B,32]
    const int*    __restrict__ stm,   // [B] int32
    const float4* __restrict__ bw,    // [256] (1024 floats)
    const float4* __restrict__ bb,
    const float4* __restrict__ Wout,  // [512] (2048 floats)
    const float*  __restrict__ bout,
    float*        __restrict__ out,   // [B]
    const int B)
{
    __shared__ int   sidx[2 * NACT];
    __shared__ float sred[THREADS / 32];

    const int tid   = threadIdx.x;
    const int persp = tid >> 7;        // 0 = white, 1 = black
    const int t     = tid & 127;       // 8-column group within the perspective
    const unsigned* tab  = g_q + (unsigned)persp * (NFEAT * WPR) + (unsigned)t * 4u;
    const int*      idxs = sidx + persp * NACT;

    // Loop-invariant epilogue operands.
    const float4* bias = (persp == 0) ? bw : bb;
    const float4 bv0 = bias[t * 2];
    const float4 bv1 = bias[t * 2 + 1];
    const float  bo  = bout[0];

    for (int b = blockIdx.x; b < B; b += GRID_P) {
        // Stage indices. Safe without a leading sync: all reads of sidx from
        // the previous iteration happen before its trailing __syncthreads.
        if (tid < NACT)          sidx[tid] = fw[b * NACT + tid];
        else if (tid < 2 * NACT) sidx[tid] = fb[b * NACT + (tid - NACT)];
        __syncthreads();

        // Two partial SIMD accumulators (16 features each): no i16 overflow.
        uint4 a0 = make_uint4(0u, 0u, 0u, 0u);
        uint4 a1 = make_uint4(0u, 0u, 0u, 0u);

        #pragma unroll 8
        for (int i = 0; i < 16; ++i) {
            int f = idxs[i];
            if (f >= 0) {
                uint4 v = *(const uint4*)(tab + (unsigned)f * WPR);
                a0.x = __vadd2(a0.x, v.x);  a0.y = __vadd2(a0.y, v.y);
                a0.z = __vadd2(a0.z, v.z);  a0.w = __vadd2(a0.w, v.w);
            }
        }
        #pragma unroll 8
        for (int i = 16; i < 32; ++i) {
            int f = idxs[i];
            if (f >= 0) {
                uint4 v = *(const uint4*)(tab + (unsigned)f * WPR);
                a1.x = __vadd2(a1.x, v.x);  a1.y = __vadd2(a1.y, v.y);
                a1.z = __vadd2(a1.z, v.z);  a1.w = __vadd2(a1.w, v.w);
            }
        }

        // Epilogue: exact int32 combine, dequant, bias, clip^2, dot.
        const bool white = (__ldg(&stm[b]) != 0);
        const int half = ((persp == 0) == white) ? 0 : 256;   // float4 offset
        const float4 w0 = Wout[half + t * 2];
        const float4 w1 = Wout[half + t * 2 + 1];

        #define COL(wA, wB, EXT, bvc, wc)                               \
            ({ int   _c = EXT(wA) + EXT(wB);                            \
               float _h = fmaf((float)_c, QINV, (bvc));                 \
               _h = fminf(fmaxf(_h, 0.0f), 1.0f);                       \
               _h * _h * (wc); })

        float p = 0.0f;
        p += COL(a0.x, a1.x, lo16, bv0.x, w0.x);
        p += COL(a0.x, a1.x, hi16, bv0.y, w0.y);
        p += COL(a0.y, a1.y, lo16, bv0.z, w0.z);
        p += COL(a0.y, a1.y, hi16, bv0.w, w0.w);
        p += COL(a0.z, a1.z, lo16, bv1.x, w1.x);
        p += COL(a0.z, a1.z, hi16, bv1.y, w1.y);
        p += COL(a0.w, a1.w, lo16, bv1.z, w1.z);
        p += COL(a0.w, a1.w, hi16, bv1.w, w1.w);
        #undef COL

        // Block reduction.
        #pragma unroll
        for (int o = 16; o > 0; o >>= 1)
            p += __shfl_down_sync(0xffffffffu, p, o);
        if ((tid & 31) == 0) sred[tid >> 5] = p;
        __syncthreads();
        // tid0 reads sred here; the next write to sred (next iteration)
        // happens only after the staging __syncthreads above, which tid0
        // must also pass -> no race, no extra barrier needed.
        if (tid == 0) {
            float s = 0.0f;
            #pragma unroll
            for (int k = 0; k < THREADS / 32; ++k) s += sred[k];
            out[b] = s + bo;
        }
    }
}

extern "C" void kernel_launch(void* const* d_in, const int* in_sizes, int n_in,
                              void* d_out, int out_size)
{
    const int*    fw   = (const int*)d_in[0];
    const int*    fb   = (const int*)d_in[1];
    const int*    stm  = (const int*)d_in[2];
    const float2* Ww   = (const float2*)d_in[3];
    const float4* bw   = (const float4*)d_in[4];
    const float2* Wb   = (const float2*)d_in[5];
    const float4* bb   = (const float4*)d_in[6];
    const float4* Wout = (const float4*)d_in[7];
    const float*  bout = (const float*)d_in[8];
    float*        out  = (float*)d_out;

    const int B = in_sizes[0] / NACT;   // 16384

    const unsigned nwords = NFEAT * WPR;
    convert_kernel<<<(nwords + 255) / 256, 256>>>(Ww, Wb);
    nnue_gather_kernel<<<GRID_P, THREADS>>>(fw, fb, stm, bw, bb, Wout, bout,
                                            out, B);
}

// round 16
// speedup vs baseline: 1.0723x; 1.0723x over previous
#include <cuda_runtime.h>
#include <cuda_bf16.h>
#include <cstdint>

// PerspectiveNet768x2 — FINAL CHAMPION: int16 fixed-point gather.
//
// Certified across 14 measured rounds. The kernel is bound by the per-SM
// global-load return path (~70 B/cyc/SM ≈ 19.7 TB/s chip-wide), a ceiling
// shown invariant to: load width (LDG.128 ≡ LDG.64), predication vs
// branch-free, occupancy (60-98%), CTA granularity (1-2 pos, persistent),
// L1 policy (__ldcs), and TMA/SMEM routing (3 attempts, all regressions).
// The single real optimization is fp32 -> int16 table quantization, halving
// gathered bytes (213us -> 120us).
//
// Numerics: scale 40940 = 2047/0.05 (|w| < 0.05 -> |q| <= 2047); two vadd2
// SIMD partial accumulators of 16 features each (max |partial| = 16*2047 =
// 32752 < 32767, no int16 overflow); exact int32 combine; fp32 dequant +
// bias + clip^2 + output dot. Measured rel_err 2.560972e-4 (gate 1e-3).

#define NACT        32
#define THREADS     256
#define NFEAT       3840
#define WPR         512u            // words per row: 1024 cols as int16 pairs
#define QSCALE      40940.0f        // 2047 / 0.05
#define QINV        (1.0f / 40940.0f)

__device__ unsigned g_q[2u * NFEAT * WPR];   // [white|black] packed int16 pairs

__global__ void convert_kernel(const float2* __restrict__ Ww,
                               const float2* __restrict__ Wb)
{
    const unsigned n = NFEAT * WPR;
    unsigned i = blockIdx.x * blockDim.x + threadIdx.x;
    if (i >= n) return;
    float2 a = __ldg(&Ww[i]);
    int q0 = __float2int_rn(a.x * QSCALE);
    int q1 = __float2int_rn(a.y * QSCALE);
    g_q[i] = ((unsigned)q0 & 0xFFFFu) | ((unsigned)q1 << 16);
    float2 c = __ldg(&Wb[i]);
    int p0 = __float2int_rn(c.x * QSCALE);
    int p1 = __float2int_rn(c.y * QSCALE);
    g_q[n + i] = ((unsigned)p0 & 0xFFFFu) | ((unsigned)p1 << 16);
}

__device__ __forceinline__ int lo16(unsigned w) { return (int)((short)(w & 0xFFFFu)); }
__device__ __forceinline__ int hi16(unsigned w) { return (int)((short)(w >> 16)); }

__global__ __launch_bounds__(THREADS)
void nnue_gather_kernel(
    const int*    __restrict__ fw,    // [B,32]
    const int*    __restrict__ fb,    // [B,32]
    const int*    __restrict__ stm,   // [B] int32
    const float4* __restrict__ bw,    // [256] (1024 floats)
    const float4* __restrict__ bb,
    const float4* __restrict__ Wout,  // [512] (2048 floats)
    const float*  __restrict__ bout,
    float*        __restrict__ out)   // [B]
{
    __shared__ int   sidx[2 * NACT];
    __shared__ float sred[THREADS / 32];

    const int b   = blockIdx.x;
    const int tid = threadIdx.x;

    if (tid < NACT)          sidx[tid] = fw[b * NACT + tid];
    else if (tid < 2 * NACT) sidx[tid] = fb[b * NACT + (tid - NACT)];
    __syncthreads();

    const int persp = tid >> 7;        // 0 = white, 1 = black
    const int t     = tid & 127;       // 8-column group within the perspective
    const unsigned* tab  = g_q + (unsigned)persp * (NFEAT * WPR) + (unsigned)t * 4u;
    const int*      idxs = sidx + persp * NACT;

    // Two partial SIMD accumulators (16 features each) -> no 16-bit overflow.
    uint4 a0 = make_uint4(0u, 0u, 0u, 0u);
    uint4 a1 = make_uint4(0u, 0u, 0u, 0u);

    #pragma unroll 8
    for (int i = 0; i < 16; ++i) {
        int f = idxs[i];
        if (f >= 0) {
            uint4 v = *(const uint4*)(tab + (unsigned)f * WPR);
            a0.x = __vadd2(a0.x, v.x);  a0.y = __vadd2(a0.y, v.y);
            a0.z = __vadd2(a0.z, v.z);  a0.w = __vadd2(a0.w, v.w);
        }
    }
    #pragma unroll 8
    for (int i = 16; i < 32; ++i) {
        int f = idxs[i];
        if (f >= 0) {
            uint4 v = *(const uint4*)(tab + (unsigned)f * WPR);
            a1.x = __vadd2(a1.x, v.x);  a1.y = __vadd2(a1.y, v.y);
            a1.z = __vadd2(a1.z, v.z);  a1.w = __vadd2(a1.w, v.w);
        }
    }

    // Epilogue: combine partials in int32 (exact), dequant, bias, clip^2, dot.
    const bool white = (__ldg(&stm[b]) != 0);
    const float4* bias = (persp == 0) ? bw : bb;
    const float4 bv0 = bias[t * 2];
    const float4 bv1 = bias[t * 2 + 1];
    // This thread's 8 hidden cols map to W_out's first half iff
    // (its perspective is white) == (stm is white).
    const int half = ((persp == 0) == white) ? 0 : 256;   // float4 offset
    const float4 w0 = Wout[half + t * 2];
    const float4 w1 = Wout[half + t * 2 + 1];

    #define COL(wA, wB, EXT, bvc, wc)                                   \
        ({ int   _c = EXT(wA) + EXT(wB);                                \
           float _h = fmaf((float)_c, QINV, (bvc));                     \
           _h = fminf(fmaxf(_h, 0.0f), 1.0f);                           \
           _h * _h * (wc); })

    float p = 0.0f;
    p += COL(a0.x, a1.x, lo16, bv0.x, w0.x);
    p += COL(a0.x, a1.x, hi16, bv0.y, w0.y);
    p += COL(a0.y, a1.y, lo16, bv0.z, w0.z);
    p += COL(a0.y, a1.y, hi16, bv0.w, w0.w);
    p += COL(a0.z, a1.z, lo16, bv1.x, w1.x);
    p += COL(a0.z, a1.z, hi16, bv1.y, w1.y);
    p += COL(a0.w, a1.w, lo16, bv1.z, w1.z);
    p += COL(a0.w, a1.w, hi16, bv1.w, w1.w);
    #undef COL

    // Block reduction: warp shuffle, then 8 partials through smem.
    #pragma unroll
    for (int o = 16; o > 0; o >>= 1)
        p += __shfl_down_sync(0xffffffffu, p, o);
    if ((tid & 31) == 0) sred[tid >> 5] = p;
    __syncthreads();

    if (tid == 0) {
        float s = 0.0f;
        #pragma unroll
        for (int k = 0; k < THREADS / 32; ++k) s += sred[k];
        out[b] = s + bout[0];
    }
}

extern "C" void kernel_launch(void* const* d_in, const int* in_sizes, int n_in,
                              void* d_out, int out_size)
{
    const int*    fw   = (const int*)d_in[0];
    const int*    fb   = (const int*)d_in[1];
    const int*    stm  = (const int*)d_in[2];
    const float2* Ww   = (const float2*)d_in[3];
    const float4* bw   = (const float4*)d_in[4];
    const float2* Wb   = (const float2*)d_in[5];
    const float4* bb   = (const float4*)d_in[6];
    const float4* Wout = (const float4*)d_in[7];
    const float*  bout = (const float*)d_in[8];
    float*        out  = (float*)d_out;

    const int B = in_sizes[0] / NACT;   // 16384

    const unsigned nwords = NFEAT * WPR;
    convert_kernel<<<(nwords + 255) / 256, 256>>>(Ww, Wb);
    nnue_gather_kernel<<<B, THREADS>>>(fw, fb, stm, bw, bb, Wout, bout, out);
}